// round 2
// baseline (speedup 1.0000x reference)
#include <cuda_runtime.h>
#include <cuda_bf16.h>
#include <math.h>

#define NUM_SRC   200000
#define NUM_DST   100000
#define NUM_EDGES 1600000
#define IN_DIM    128
#define HID       256
#define OUT_DIM   128

// Scratch (allocation-free rule: __device__ globals)
__device__ __align__(16) float g_accum[(size_t)NUM_DST * IN_DIM];  // 51.2 MB
__device__ __align__(16) float g_cnt[NUM_DST];                     // 0.4 MB
__device__ __align__(16) float g_h[(size_t)NUM_DST * HID];         // 102.4 MB

// ---------------------------------------------------------------------------
// K0: zero accum + cnt
// ---------------------------------------------------------------------------
__global__ void zero_kernel() {
    const int n4_accum = (NUM_DST * IN_DIM) / 4;   // 3,200,000 float4
    const int n4_cnt   = NUM_DST / 4;              // 25,000 float4
    float4 z = make_float4(0.f, 0.f, 0.f, 0.f);
    int stride = gridDim.x * blockDim.x;
    for (int i = blockIdx.x * blockDim.x + threadIdx.x; i < n4_accum; i += stride)
        ((float4*)g_accum)[i] = z;
    for (int i = blockIdx.x * blockDim.x + threadIdx.x; i < n4_cnt; i += stride)
        ((float4*)g_cnt)[i] = z;
}

// ---------------------------------------------------------------------------
// K1: edge scatter-add. One warp per edge, one float4 per lane.
// NOTE: edge indices are int32 (JAX x64 disabled downgrades int64 -> int32).
// ---------------------------------------------------------------------------
__global__ void edge_kernel(const float* __restrict__ x,
                            const int* __restrict__ esrc,
                            const int* __restrict__ edst) {
    int e    = blockIdx.x * 8 + (threadIdx.x >> 5);
    int lane = threadIdx.x & 31;
    if (e >= NUM_EDGES) return;
    int s = __ldg(esrc + e);
    int d = __ldg(edst + e);
    float4 v = __ldg(((const float4*)(x + (size_t)s * IN_DIM)) + lane);
    float* outp = g_accum + (size_t)d * IN_DIM + lane * 4;
    asm volatile("red.global.add.v4.f32 [%0], {%1,%2,%3,%4};"
                 :: "l"(outp), "f"(v.x), "f"(v.y), "f"(v.z), "f"(v.w) : "memory");
    if (lane == 0) {
        float one = 1.0f;
        asm volatile("red.global.add.f32 [%0], %1;" :: "l"(g_cnt + d), "f"(one) : "memory");
    }
}

// ---------------------------------------------------------------------------
// K2: h_raw = mean_nbr @ w_l + x_tgt @ w_r + b_l   -> g_h
// Block: 64 rows x 256 cols, 256 threads. Thread tile: 16 rows x 4 cols.
// ---------------------------------------------------------------------------
__global__ void gemm1_kernel(const float* __restrict__ x,
                             const float* __restrict__ w_l,
                             const float* __restrict__ b_l,
                             const float* __restrict__ w_r) {
    __shared__ float sA[64 * 128];   // 32 KB
    int row0 = blockIdx.x * 64;
    int tid  = threadIdx.x;
    int tx   = tid & 63;             // col group: cols [4*tx, 4*tx+4)
    int ty   = tid >> 6;             // row group: rows [16*ty, 16*ty+16)

    float4 bv = __ldg(((const float4*)b_l) + tx);
    float4 acc[16];
#pragma unroll
    for (int i = 0; i < 16; ++i) acc[i] = bv;

    // ---- pass 1: A = mean_nbr (accum / max(cnt,1)) ----
    for (int j = tid; j < 64 * 32; j += 256) {      // float4 units
        int r = j >> 5, c4 = j & 31;
        int row = row0 + r;
        float4 v = make_float4(0.f, 0.f, 0.f, 0.f);
        if (row < NUM_DST) {
            float inv = 1.0f / fmaxf(g_cnt[row], 1.0f);
            float4 a = ((const float4*)g_accum)[(size_t)row * 32 + c4];
            v.x = a.x * inv; v.y = a.y * inv; v.z = a.z * inv; v.w = a.w * inv;
        }
        ((float4*)sA)[r * 32 + c4] = v;
    }
    __syncthreads();

    const float4* wl4 = (const float4*)w_l;   // [128][64] float4 rows
#pragma unroll 4
    for (int k = 0; k < 128; ++k) {
        float4 wv = __ldg(wl4 + k * 64 + tx);
#pragma unroll
        for (int i = 0; i < 16; ++i) {
            float a = sA[(ty * 16 + i) * 128 + k];
            acc[i].x += a * wv.x; acc[i].y += a * wv.y;
            acc[i].z += a * wv.z; acc[i].w += a * wv.w;
        }
    }
    __syncthreads();

    // ---- pass 2: A = x_tgt ----
    for (int j = tid; j < 64 * 32; j += 256) {
        int r = j >> 5, c4 = j & 31;
        int row = row0 + r;
        float4 v = make_float4(0.f, 0.f, 0.f, 0.f);
        if (row < NUM_DST)
            v = __ldg(((const float4*)x) + (size_t)row * 32 + c4);
        ((float4*)sA)[r * 32 + c4] = v;
    }
    __syncthreads();

    const float4* wr4 = (const float4*)w_r;
#pragma unroll 4
    for (int k = 0; k < 128; ++k) {
        float4 wv = __ldg(wr4 + k * 64 + tx);
#pragma unroll
        for (int i = 0; i < 16; ++i) {
            float a = sA[(ty * 16 + i) * 128 + k];
            acc[i].x += a * wv.x; acc[i].y += a * wv.y;
            acc[i].z += a * wv.z; acc[i].w += a * wv.w;
        }
    }

    // ---- store ----
#pragma unroll
    for (int i = 0; i < 16; ++i) {
        int row = row0 + ty * 16 + i;
        if (row < NUM_DST)
            ((float4*)g_h)[(size_t)row * 64 + tx] = acc[i];
    }
}

// ---------------------------------------------------------------------------
// K3: g_h = gelu(layer_norm(g_h, ln1_g, ln1_b)) in place. One warp per row.
// ---------------------------------------------------------------------------
__global__ void ln_gelu_kernel(const float* __restrict__ ln_g,
                               const float* __restrict__ ln_b) {
    int row  = blockIdx.x * 8 + (threadIdx.x >> 5);
    int lane = threadIdx.x & 31;
    if (row >= NUM_DST) return;

    float4* hp = ((float4*)g_h) + (size_t)row * 64;
    float4 a = hp[lane];
    float4 b = hp[32 + lane];

    float s  = a.x + a.y + a.z + a.w + b.x + b.y + b.z + b.w;
    float sq = a.x*a.x + a.y*a.y + a.z*a.z + a.w*a.w
             + b.x*b.x + b.y*b.y + b.z*b.z + b.w*b.w;
#pragma unroll
    for (int off = 16; off > 0; off >>= 1) {
        s  += __shfl_xor_sync(0xffffffffu, s,  off);
        sq += __shfl_xor_sync(0xffffffffu, sq, off);
    }
    float mu   = s * (1.0f / HID);
    float var  = sq * (1.0f / HID) - mu * mu;
    float rstd = rsqrtf(var + 1e-5f);

    float4 ga = __ldg(((const float4*)ln_g) + lane);
    float4 gb = __ldg(((const float4*)ln_g) + 32 + lane);
    float4 ba = __ldg(((const float4*)ln_b) + lane);
    float4 bb = __ldg(((const float4*)ln_b) + 32 + lane);

#define LNG(v, g, bo) do {                                        \
        float t = (v - mu) * rstd * (g) + (bo);                   \
        v = 0.5f * t * (1.0f + erff(t * 0.70710678118654752f));   \
    } while (0)
    LNG(a.x, ga.x, ba.x); LNG(a.y, ga.y, ba.y); LNG(a.z, ga.z, ba.z); LNG(a.w, ga.w, ba.w);
    LNG(b.x, gb.x, bb.x); LNG(b.y, gb.y, bb.y); LNG(b.z, gb.z, bb.z); LNG(b.w, gb.w, bb.w);
#undef LNG

    hp[lane]      = a;
    hp[32 + lane] = b;
}

// ---------------------------------------------------------------------------
// K4: out_raw = g_h @ w_out + b_out  -> d_out
// Block: 64 rows x 128 cols, 256 threads. Thread tile: 8 rows x 4 cols.
// K=256 processed in two 128-wide passes through smem.
// ---------------------------------------------------------------------------
__global__ void gemm2_kernel(const float* __restrict__ w_out,
                             const float* __restrict__ b_out,
                             float* __restrict__ out) {
    __shared__ float sH[64 * 128];   // 32 KB
    int row0 = blockIdx.x * 64;
    int tid  = threadIdx.x;
    int tx   = tid & 31;             // cols [4*tx, 4*tx+4)
    int ty   = tid >> 5;             // rows [8*ty, 8*ty+8)

    float4 bv = __ldg(((const float4*)b_out) + tx);
    float4 acc[8];
#pragma unroll
    for (int i = 0; i < 8; ++i) acc[i] = bv;

    const float4* wo4 = (const float4*)w_out;   // [256][32] float4 rows

    for (int pass = 0; pass < 2; ++pass) {
        for (int j = tid; j < 64 * 32; j += 256) {
            int r = j >> 5, c4 = j & 31;
            int row = row0 + r;
            float4 v = make_float4(0.f, 0.f, 0.f, 0.f);
            if (row < NUM_DST)
                v = ((const float4*)g_h)[(size_t)row * 64 + pass * 32 + c4];
            ((float4*)sH)[r * 32 + c4] = v;
        }
        __syncthreads();

#pragma unroll 4
        for (int k = 0; k < 128; ++k) {
            float4 wv = __ldg(wo4 + (pass * 128 + k) * 32 + tx);
#pragma unroll
            for (int i = 0; i < 8; ++i) {
                float a = sH[(ty * 8 + i) * 128 + k];
                acc[i].x += a * wv.x; acc[i].y += a * wv.y;
                acc[i].z += a * wv.z; acc[i].w += a * wv.w;
            }
        }
        __syncthreads();
    }

#pragma unroll
    for (int i = 0; i < 8; ++i) {
        int row = row0 + ty * 8 + i;
        if (row < NUM_DST)
            ((float4*)out)[(size_t)row * 32 + tx] = acc[i];
    }
}

// ---------------------------------------------------------------------------
// K5: d_out = layer_norm(d_out, ln2_g, ln2_b) in place. One warp per row.
// ---------------------------------------------------------------------------
__global__ void ln2_kernel(float* __restrict__ out,
                           const float* __restrict__ ln_g,
                           const float* __restrict__ ln_b) {
    int row  = blockIdx.x * 8 + (threadIdx.x >> 5);
    int lane = threadIdx.x & 31;
    if (row >= NUM_DST) return;

    float4* op = ((float4*)out) + (size_t)row * 32;
    float4 a = op[lane];

    float s  = a.x + a.y + a.z + a.w;
    float sq = a.x*a.x + a.y*a.y + a.z*a.z + a.w*a.w;
#pragma unroll
    for (int off = 16; off > 0; off >>= 1) {
        s  += __shfl_xor_sync(0xffffffffu, s,  off);
        sq += __shfl_xor_sync(0xffffffffu, sq, off);
    }
    float mu   = s * (1.0f / OUT_DIM);
    float var  = sq * (1.0f / OUT_DIM) - mu * mu;
    float rstd = rsqrtf(var + 1e-5f);

    float4 g = __ldg(((const float4*)ln_g) + lane);
    float4 b = __ldg(((const float4*)ln_b) + lane);

    a.x = (a.x - mu) * rstd * g.x + b.x;
    a.y = (a.y - mu) * rstd * g.y + b.y;
    a.z = (a.z - mu) * rstd * g.z + b.z;
    a.w = (a.w - mu) * rstd * g.w + b.w;

    op[lane] = a;
}

// ---------------------------------------------------------------------------
extern "C" void kernel_launch(void* const* d_in, const int* in_sizes, int n_in,
                              void* d_out, int out_size) {
    const float* x     = (const float*)d_in[0];
    const float* w_l   = (const float*)d_in[1];
    const float* b_l   = (const float*)d_in[2];
    const float* w_r   = (const float*)d_in[3];
    const float* ln1_g = (const float*)d_in[4];
    const float* ln1_b = (const float*)d_in[5];
    const float* w_out = (const float*)d_in[6];
    const float* b_out = (const float*)d_in[7];
    const float* ln2_g = (const float*)d_in[8];
    const float* ln2_b = (const float*)d_in[9];
    const int*   esrc  = (const int*)d_in[10];
    const int*   edst  = (const int*)d_in[11];
    float* out = (float*)d_out;

    zero_kernel<<<1024, 256>>>();
    edge_kernel<<<NUM_EDGES / 8, 256>>>(x, esrc, edst);

    int gblocks = (NUM_DST + 63) / 64;   // 1563
    gemm1_kernel<<<gblocks, 256>>>(x, w_l, b_l, w_r);
    ln_gelu_kernel<<<(NUM_DST + 7) / 8, 256>>>(ln1_g, ln1_b);
    gemm2_kernel<<<gblocks, 256>>>(w_out, b_out, out);
    ln2_kernel<<<(NUM_DST + 7) / 8, 256>>>(out, ln2_g, ln2_b);
}

// round 4
// speedup vs baseline: 1.1088x; 1.1088x over previous
#include <cuda_runtime.h>
#include <cuda_bf16.h>
#include <math.h>

#define NUM_SRC   200000
#define NUM_DST   100000
#define NUM_EDGES 1600000
#define IN_DIM    128
#define HID       256
#define OUT_DIM   128

typedef unsigned long long ull;

// Scratch (allocation-free rule: __device__ globals)
__device__ __align__(16) float g_accum[(size_t)NUM_DST * IN_DIM];  // 51.2 MB
__device__ __align__(16) float g_cnt[NUM_DST];                     // 0.4 MB
__device__ __align__(16) float g_h[(size_t)NUM_DST * HID];         // 102.4 MB

// ---------------------------------------------------------------------------
// helpers: packed f32x2 FMA
// ---------------------------------------------------------------------------
__device__ __forceinline__ ull dup2(float v) {
    ull r; unsigned u = __float_as_uint(v);
    asm("mov.b64 %0, {%1, %1};" : "=l"(r) : "r"(u));
    return r;
}
__device__ __forceinline__ void fma2(ull& d, ull a, ull b) {
    asm("fma.rn.f32x2 %0, %1, %2, %0;" : "+l"(d) : "l"(a), "l"(b));
}
__device__ __forceinline__ float exhalf(ull v, int h) {
    return __uint_as_float((unsigned)(h ? (v >> 32) : v));
}
__device__ __forceinline__ float gelu_exact(float t) {
    return 0.5f * t * (1.0f + erff(t * 0.70710678118654752f));
}

// ---------------------------------------------------------------------------
// K0: zero accum + cnt
// ---------------------------------------------------------------------------
__global__ void zero_kernel() {
    const int n4_accum = (NUM_DST * IN_DIM) / 4;
    const int n4_cnt   = NUM_DST / 4;
    float4 z = make_float4(0.f, 0.f, 0.f, 0.f);
    int stride = gridDim.x * blockDim.x;
    for (int i = blockIdx.x * blockDim.x + threadIdx.x; i < n4_accum; i += stride)
        ((float4*)g_accum)[i] = z;
    for (int i = blockIdx.x * blockDim.x + threadIdx.x; i < n4_cnt; i += stride)
        ((float4*)g_cnt)[i] = z;
}

// ---------------------------------------------------------------------------
// K1: edge scatter-add. One warp per edge, one float4 per lane. int32 indices.
// ---------------------------------------------------------------------------
__global__ void edge_kernel(const float* __restrict__ x,
                            const int* __restrict__ esrc,
                            const int* __restrict__ edst) {
    int e    = blockIdx.x * 8 + (threadIdx.x >> 5);
    int lane = threadIdx.x & 31;
    if (e >= NUM_EDGES) return;
    int s = __ldg(esrc + e);
    int d = __ldg(edst + e);
    float4 v = __ldg(((const float4*)(x + (size_t)s * IN_DIM)) + lane);
    float* outp = g_accum + (size_t)d * IN_DIM + lane * 4;
    asm volatile("red.global.add.v4.f32 [%0], {%1,%2,%3,%4};"
                 :: "l"(outp), "f"(v.x), "f"(v.y), "f"(v.z), "f"(v.w) : "memory");
    if (lane == 0) {
        float one = 1.0f;
        asm volatile("red.global.add.f32 [%0], %1;" :: "l"(g_cnt + d), "f"(one) : "memory");
    }
}

// ---------------------------------------------------------------------------
// K2: g_h = gelu(LN1(mean_nbr @ w_l + b_l + x_tgt @ w_r))   (fused epilogue)
// Block: 64 rows x 256 cols, 256 threads. Thread: 16 rows (8 pairs) x 4 cols.
// A tile in smem, row-pair interleaved: word(row,k) = (row>>1)*256 + 2k + (row&1)
// so ld.shared.b64 yields {A[2p][k], A[2p+1][k]} for FFMA2.
// ---------------------------------------------------------------------------
__global__ __launch_bounds__(256) void gemm1_kernel(
        const float* __restrict__ x,
        const float* __restrict__ w_l,
        const float* __restrict__ b_l,
        const float* __restrict__ w_r,
        const float* __restrict__ ln_g,
        const float* __restrict__ ln_b) {
    __shared__ float  sA[8192];            // 32 KB, interleaved pairs
    __shared__ float2 sRed[2][4][16];      // per-warp-half row partials

    int row0 = blockIdx.x * 64;
    int tid  = threadIdx.x;
    int tx   = tid & 63;      // col group: cols [4tx, 4tx+4)
    int ty   = tid >> 6;      // row group: rows [16ty, 16ty+16)
    int lane = tid & 31;
    int wh   = tx >> 5;       // which half of the 64-thread row set

    float4 bv = __ldg(((const float4*)b_l) + tx);
    ull acc[8][4];
#pragma unroll
    for (int p = 0; p < 8; ++p) {
        acc[p][0] = dup2(bv.x); acc[p][1] = dup2(bv.y);
        acc[p][2] = dup2(bv.z); acc[p][3] = dup2(bv.w);
    }

    // ---- pass 1 staging: A = mean_nbr ----
    for (int j = tid; j < 2048; j += 256) {
        int r = j >> 5, c4 = j & 31;
        int row = row0 + r;
        float4 v = make_float4(0.f, 0.f, 0.f, 0.f);
        if (row < NUM_DST) {
            float inv = 1.0f / fmaxf(g_cnt[row], 1.0f);
            float4 a = ((const float4*)g_accum)[(size_t)row * 32 + c4];
            v.x = a.x * inv; v.y = a.y * inv; v.z = a.z * inv; v.w = a.w * inv;
        }
        int base = (r >> 1) * 256 + (r & 1);
        sA[base + (4 * c4 + 0) * 2] = v.x;
        sA[base + (4 * c4 + 1) * 2] = v.y;
        sA[base + (4 * c4 + 2) * 2] = v.z;
        sA[base + (4 * c4 + 3) * 2] = v.w;
    }
    __syncthreads();

    const ull* sA2 = (const ull*)sA;
    {
        const float4* w4 = (const float4*)w_l;   // [128][64] float4
#pragma unroll 4
        for (int k = 0; k < 128; ++k) {
            float4 w = __ldg(w4 + k * 64 + tx);
            ull dx = dup2(w.x), dy = dup2(w.y), dz = dup2(w.z), dw = dup2(w.w);
#pragma unroll
            for (int p = 0; p < 8; ++p) {
                ull a2 = sA2[(ty * 8 + p) * 128 + k];
                fma2(acc[p][0], a2, dx); fma2(acc[p][1], a2, dy);
                fma2(acc[p][2], a2, dz); fma2(acc[p][3], a2, dw);
            }
        }
    }
    __syncthreads();

    // ---- pass 2 staging: A = x_tgt ----
    for (int j = tid; j < 2048; j += 256) {
        int r = j >> 5, c4 = j & 31;
        int row = row0 + r;
        float4 v = make_float4(0.f, 0.f, 0.f, 0.f);
        if (row < NUM_DST)
            v = __ldg(((const float4*)x) + (size_t)row * 32 + c4);
        int base = (r >> 1) * 256 + (r & 1);
        sA[base + (4 * c4 + 0) * 2] = v.x;
        sA[base + (4 * c4 + 1) * 2] = v.y;
        sA[base + (4 * c4 + 2) * 2] = v.z;
        sA[base + (4 * c4 + 3) * 2] = v.w;
    }
    __syncthreads();

    {
        const float4* w4 = (const float4*)w_r;
#pragma unroll 4
        for (int k = 0; k < 128; ++k) {
            float4 w = __ldg(w4 + k * 64 + tx);
            ull dx = dup2(w.x), dy = dup2(w.y), dz = dup2(w.z), dw = dup2(w.w);
#pragma unroll
            for (int p = 0; p < 8; ++p) {
                ull a2 = sA2[(ty * 8 + p) * 128 + k];
                fma2(acc[p][0], a2, dx); fma2(acc[p][1], a2, dy);
                fma2(acc[p][2], a2, dz); fma2(acc[p][3], a2, dw);
            }
        }
    }

    // ---- fused epilogue: LN1 + GELU ----
#pragma unroll
    for (int i = 0; i < 16; ++i) {
        int p = i >> 1, h = i & 1;
        float c0 = exhalf(acc[p][0], h), c1 = exhalf(acc[p][1], h);
        float c2 = exhalf(acc[p][2], h), c3 = exhalf(acc[p][3], h);
        float s  = c0 + c1 + c2 + c3;
        float sq = c0*c0 + c1*c1 + c2*c2 + c3*c3;
#pragma unroll
        for (int o = 16; o > 0; o >>= 1) {
            s  += __shfl_xor_sync(0xffffffffu, s,  o);
            sq += __shfl_xor_sync(0xffffffffu, sq, o);
        }
        if (lane == 0) sRed[wh][ty][i] = make_float2(s, sq);
    }
    __syncthreads();

    float4 lg = __ldg(((const float4*)ln_g) + tx);
    float4 lb = __ldg(((const float4*)ln_b) + tx);
#pragma unroll
    for (int i = 0; i < 16; ++i) {
        int row = row0 + ty * 16 + i;
        if (row >= NUM_DST) continue;
        float2 A = sRed[0][ty][i], B = sRed[1][ty][i];
        float mu   = (A.x + B.x) * (1.0f / HID);
        float var  = (A.y + B.y) * (1.0f / HID) - mu * mu;
        float rstd = rsqrtf(var + 1e-5f);
        int p = i >> 1, h = i & 1;
        float4 o;
        o.x = gelu_exact((exhalf(acc[p][0], h) - mu) * rstd * lg.x + lb.x);
        o.y = gelu_exact((exhalf(acc[p][1], h) - mu) * rstd * lg.y + lb.y);
        o.z = gelu_exact((exhalf(acc[p][2], h) - mu) * rstd * lg.z + lb.z);
        o.w = gelu_exact((exhalf(acc[p][3], h) - mu) * rstd * lg.w + lb.w);
        ((float4*)g_h)[(size_t)row * 64 + tx] = o;
    }
}

// ---------------------------------------------------------------------------
// K3: out = LN2(g_h @ w_out + b_out)   (fused epilogue)
// Block: 64 rows x 128 cols, 256 threads. Thread: 8 rows (4 pairs) x 4 cols.
// K=256 in two 128-wide passes. One warp owns a full 128-col row set.
// ---------------------------------------------------------------------------
__global__ __launch_bounds__(256) void gemm2_kernel(
        const float* __restrict__ w_out,
        const float* __restrict__ b_out,
        const float* __restrict__ ln_g,
        const float* __restrict__ ln_b,
        float* __restrict__ out) {
    __shared__ float sH[8192];   // 32 KB interleaved pairs

    int row0 = blockIdx.x * 64;
    int tid  = threadIdx.x;
    int tx   = tid & 31;      // cols [4tx, 4tx+4)
    int ty   = tid >> 5;      // rows [8ty, 8ty+8)

    float4 bv = __ldg(((const float4*)b_out) + tx);
    ull acc[4][4];
#pragma unroll
    for (int p = 0; p < 4; ++p) {
        acc[p][0] = dup2(bv.x); acc[p][1] = dup2(bv.y);
        acc[p][2] = dup2(bv.z); acc[p][3] = dup2(bv.w);
    }

    const ull*    sH2 = (const ull*)sH;
    const float4* wo4 = (const float4*)w_out;   // [256][32] float4

    for (int pass = 0; pass < 2; ++pass) {
        for (int j = tid; j < 2048; j += 256) {
            int r = j >> 5, c4 = j & 31;
            int row = row0 + r;
            float4 v = make_float4(0.f, 0.f, 0.f, 0.f);
            if (row < NUM_DST)
                v = ((const float4*)g_h)[(size_t)row * 64 + pass * 32 + c4];
            int base = (r >> 1) * 256 + (r & 1);
            sH[base + (4 * c4 + 0) * 2] = v.x;
            sH[base + (4 * c4 + 1) * 2] = v.y;
            sH[base + (4 * c4 + 2) * 2] = v.z;
            sH[base + (4 * c4 + 3) * 2] = v.w;
        }
        __syncthreads();

#pragma unroll 4
        for (int k = 0; k < 128; ++k) {
            float4 w = __ldg(wo4 + (pass * 128 + k) * 32 + tx);
            ull dx = dup2(w.x), dy = dup2(w.y), dz = dup2(w.z), dw = dup2(w.w);
#pragma unroll
            for (int p = 0; p < 4; ++p) {
                ull a2 = sH2[(ty * 4 + p) * 128 + k];
                fma2(acc[p][0], a2, dx); fma2(acc[p][1], a2, dy);
                fma2(acc[p][2], a2, dz); fma2(acc[p][3], a2, dw);
            }
        }
        __syncthreads();
    }

    // ---- fused epilogue: LN2. Full row lives in one warp. ----
    float4 lg = __ldg(((const float4*)ln_g) + tx);
    float4 lb = __ldg(((const float4*)ln_b) + tx);
#pragma unroll
    for (int i = 0; i < 8; ++i) {
        int p = i >> 1, h = i & 1;
        float c0 = exhalf(acc[p][0], h), c1 = exhalf(acc[p][1], h);
        float c2 = exhalf(acc[p][2], h), c3 = exhalf(acc[p][3], h);
        float s  = c0 + c1 + c2 + c3;
        float sq = c0*c0 + c1*c1 + c2*c2 + c3*c3;
#pragma unroll
        for (int o = 16; o > 0; o >>= 1) {
            s  += __shfl_xor_sync(0xffffffffu, s,  o);
            sq += __shfl_xor_sync(0xffffffffu, sq, o);
        }
        float mu   = s * (1.0f / OUT_DIM);
        float var  = sq * (1.0f / OUT_DIM) - mu * mu;
        float rstd = rsqrtf(var + 1e-5f);

        int row = row0 + ty * 8 + i;
        if (row < NUM_DST) {
            float4 o4;
            o4.x = (c0 - mu) * rstd * lg.x + lb.x;
            o4.y = (c1 - mu) * rstd * lg.y + lb.y;
            o4.z = (c2 - mu) * rstd * lg.z + lb.z;
            o4.w = (c3 - mu) * rstd * lg.w + lb.w;
            ((float4*)out)[(size_t)row * 32 + tx] = o4;
        }
    }
}

// ---------------------------------------------------------------------------
extern "C" void kernel_launch(void* const* d_in, const int* in_sizes, int n_in,
                              void* d_out, int out_size) {
    const float* x     = (const float*)d_in[0];
    const float* w_l   = (const float*)d_in[1];
    const float* b_l   = (const float*)d_in[2];
    const float* w_r   = (const float*)d_in[3];
    const float* ln1_g = (const float*)d_in[4];
    const float* ln1_b = (const float*)d_in[5];
    const float* w_out = (const float*)d_in[6];
    const float* b_out = (const float*)d_in[7];
    const float* ln2_g = (const float*)d_in[8];
    const float* ln2_b = (const float*)d_in[9];
    const int*   esrc  = (const int*)d_in[10];
    const int*   edst  = (const int*)d_in[11];
    float* out = (float*)d_out;

    zero_kernel<<<1024, 256>>>();
    edge_kernel<<<NUM_EDGES / 8, 256>>>(x, esrc, edst);

    int gblocks = (NUM_DST + 63) / 64;   // 1563
    gemm1_kernel<<<gblocks, 256>>>(x, w_l, b_l, w_r, ln1_g, ln1_b);
    gemm2_kernel<<<gblocks, 256>>>(w_out, b_out, ln2_g, ln2_b, out);
}

// round 6
// speedup vs baseline: 1.4899x; 1.3437x over previous
#include <cuda_runtime.h>
#include <cuda_bf16.h>
#include <math.h>
#include <stdint.h>

#define NUM_SRC   200000
#define NUM_DST   100000
#define NUM_EDGES 1600000
#define IN_DIM    128
#define HID       256
#define OUT_DIM   128
#define NRB       1563      // ceil(NUM_DST/64) row-blocks of 64

// ---------------------------------------------------------------------------
// Scratch (__device__ globals; no allocation allowed)
// ---------------------------------------------------------------------------
__device__ __align__(16) float    g_accum[(size_t)NUM_DST * IN_DIM];   // 51.2 MB
__device__ __align__(16) float    g_cnt[NUM_DST];                      // 0.4 MB
__device__ __align__(16) uint32_t g_hh[(size_t)NRB * 8192];            // 51.2 MB split-bf16 hi of h (frag layout)
__device__ __align__(16) uint32_t g_hl[(size_t)NRB * 8192];            // 51.2 MB split-bf16 lo of h
__device__ __align__(16) uint32_t g_whi[32768];    // W_cat hi, frag layout [kc4][ks4][nb32][lane32][w2]
__device__ __align__(16) uint32_t g_wlo[32768];    // W_cat lo
__device__ __align__(16) uint32_t g_wohi[16384];   // W_out hi, frag layout [kc4][ks4][nb16][lane32][w2]
__device__ __align__(16) uint32_t g_wolo[16384];   // W_out lo

// ---------------------------------------------------------------------------
// helpers
// ---------------------------------------------------------------------------
__device__ __forceinline__ void split2(float a0, float a1, uint32_t& hi, uint32_t& lo) {
    __nv_bfloat16 h0 = __float2bfloat16(a0), h1 = __float2bfloat16(a1);
    __nv_bfloat16 l0 = __float2bfloat16(a0 - __bfloat162float(h0));
    __nv_bfloat16 l1 = __float2bfloat16(a1 - __bfloat162float(h1));
    __nv_bfloat162 H; H.x = h0; H.y = h1;
    __nv_bfloat162 L; L.x = l0; L.y = l1;
    hi = *(uint32_t*)&H; lo = *(uint32_t*)&L;
}
__device__ __forceinline__ float gelu_exact(float t) {
    return 0.5f * t * (1.0f + erff(t * 0.70710678118654752f));
}

#define MMA(c, A0, A1, A2, A3, B0, B1)                                          \
    asm("mma.sync.aligned.m16n8k16.row.col.f32.bf16.bf16.f32 "                  \
        "{%0,%1,%2,%3},{%4,%5,%6,%7},{%8,%9},{%0,%1,%2,%3};"                    \
        : "+f"((c)[0]), "+f"((c)[1]), "+f"((c)[2]), "+f"((c)[3])                \
        : "r"(A0), "r"(A1), "r"(A2), "r"(A3), "r"(B0), "r"(B1))

// ---------------------------------------------------------------------------
// K0: zero accum + cnt
// ---------------------------------------------------------------------------
__global__ void zero_kernel() {
    const int n4_accum = (NUM_DST * IN_DIM) / 4;
    const int n4_cnt   = NUM_DST / 4;
    float4 z = make_float4(0.f, 0.f, 0.f, 0.f);
    int stride = gridDim.x * blockDim.x;
    for (int i = blockIdx.x * blockDim.x + threadIdx.x; i < n4_accum; i += stride)
        ((float4*)g_accum)[i] = z;
    for (int i = blockIdx.x * blockDim.x + threadIdx.x; i < n4_cnt; i += stride)
        ((float4*)g_cnt)[i] = z;
}

// ---------------------------------------------------------------------------
// K1: edge scatter-add. One warp per edge, one float4 per lane. int32 indices.
// ---------------------------------------------------------------------------
__global__ void edge_kernel(const float* __restrict__ x,
                            const int* __restrict__ esrc,
                            const int* __restrict__ edst) {
    int e    = blockIdx.x * 8 + (threadIdx.x >> 5);
    int lane = threadIdx.x & 31;
    if (e >= NUM_EDGES) return;
    int s = __ldg(esrc + e);
    int d = __ldg(edst + e);
    float4 v = __ldg(((const float4*)(x + (size_t)s * IN_DIM)) + lane);
    float* outp = g_accum + (size_t)d * IN_DIM + lane * 4;
    asm volatile("red.global.add.v4.f32 [%0], {%1,%2,%3,%4};"
                 :: "l"(outp), "f"(v.x), "f"(v.y), "f"(v.z), "f"(v.w) : "memory");
    if (lane == 0) {
        float one = 1.0f;
        asm volatile("red.global.add.f32 [%0], %1;" :: "l"(g_cnt + d), "f"(one) : "memory");
    }
}

// ---------------------------------------------------------------------------
// K2: prep — split weights to bf16 hi/lo in fragment layout.
// W_cat = [w_l ; w_r] : K=256 x N=256.  W_out : K=256 x N=128.
// frag index: kp = k/2 (u32 packs k even/odd), kc=kp>>5, kpl=kp&31, ks=kpl>>3,
// q=kpl&7, w=q>>2, t4=q&3, nb=n>>3, g=n&7, lane=g*4+t4.
// ---------------------------------------------------------------------------
__global__ void prep_kernel(const float* __restrict__ w_l,
                            const float* __restrict__ w_r,
                            const float* __restrict__ w_out) {
    int t = blockIdx.x * 256 + threadIdx.x;       // 0 .. 49151
    if (t < 32768) {
        int kp = t >> 8, n = t & 255;
        int k0 = 2 * kp;
        float v0, v1;
        if (k0 < 128) { v0 = w_l[k0 * 256 + n];         v1 = w_l[(k0 + 1) * 256 + n]; }
        else          { v0 = w_r[(k0 - 128) * 256 + n]; v1 = w_r[(k0 - 127) * 256 + n]; }
        uint32_t hi, lo; split2(v0, v1, hi, lo);
        int kc = kp >> 5, kpl = kp & 31, ks = kpl >> 3, q = kpl & 7;
        int w = q >> 2, t4 = q & 3, nb = n >> 3, g = n & 7;
        int idx = ((((kc * 4 + ks) * 32 + nb) * 32 + g * 4 + t4) * 2 + w);
        g_whi[idx] = hi; g_wlo[idx] = lo;
    } else {
        int u = t - 32768;
        int kp = u >> 7, n = u & 127;
        int k0 = 2 * kp;
        float v0 = w_out[k0 * 128 + n], v1 = w_out[(k0 + 1) * 128 + n];
        uint32_t hi, lo; split2(v0, v1, hi, lo);
        int kc = kp >> 5, kpl = kp & 31, ks = kpl >> 3, q = kpl & 7;
        int w = q >> 2, t4 = q & 3, nb = n >> 3, g = n & 7;
        int idx = ((((kc * 4 + ks) * 16 + nb) * 32 + g * 4 + t4) * 2 + w);
        g_wohi[idx] = hi; g_wolo[idx] = lo;
    }
}

// ---------------------------------------------------------------------------
// K3: gemm1 — h = gelu(LN1( [mean_nbr|x] @ W_cat + b_l ))  -> g_hh/g_hl
// CTA 64 rows x 256 cols, 8 warps (2m x 4n), warp tile 32x64.
// K=256 in 4 chunks of 64. 3-term split-bf16 mma.sync.
// smem (u32): Ah[2048] Al[2048] Wh[8192] Wl[8192] = 80 KB dynamic.
// ---------------------------------------------------------------------------
#define G1_SMEM (20480 * 4)
__global__ __launch_bounds__(256, 2)
void gemm1_tc(const float* __restrict__ x,
              const float* __restrict__ b_l,
              const float* __restrict__ ln_g,
              const float* __restrict__ ln_b) {
    extern __shared__ uint32_t sm[];
    uint32_t* sAh = sm;
    uint32_t* sAl = sm + 2048;
    uint32_t* sWh = sm + 4096;
    uint32_t* sWl = sm + 12288;
    __shared__ float sSum[64][4], sSq[64][4];

    int tid = threadIdx.x, wid = tid >> 5, lane = tid & 31;
    int wm = wid >> 2, wn = wid & 3;          // warp grid 2m x 4n
    int g = lane >> 2, t4 = lane & 3;
    int row0 = blockIdx.x * 64;

    float acc[2][8][4];
#pragma unroll
    for (int mt = 0; mt < 2; ++mt)
#pragma unroll
        for (int nt = 0; nt < 8; ++nt)
#pragma unroll
            for (int j = 0; j < 4; ++j) acc[mt][nt][j] = 0.f;

    for (int kc = 0; kc < 4; ++kc) {
        // ---- stage A (split fp32 -> bf16 hi/lo, frag layout) ----
        for (int u = tid; u < 2048; u += 256) {
            int r = u >> 5, kpl = u & 31;
            int grow = row0 + r;
            float a0 = 0.f, a1 = 0.f;
            if (grow < NUM_DST) {
                int k0 = (kc * 32 + kpl) * 2;
                if (k0 < 128) {
                    float inv = 1.0f / fmaxf(g_cnt[grow], 1.0f);
                    a0 = g_accum[(size_t)grow * 128 + k0] * inv;
                    a1 = g_accum[(size_t)grow * 128 + k0 + 1] * inv;
                } else {
                    a0 = __ldg(x + (size_t)grow * 128 + k0 - 128);
                    a1 = __ldg(x + (size_t)grow * 128 + k0 - 127);
                }
            }
            uint32_t hi, lo; split2(a0, a1, hi, lo);
            int ks = kpl >> 3, q = kpl & 7, w = q >> 2, tt = q & 3;
            int rb = r >> 4, h = (r >> 3) & 1, gg = r & 7;
            int idx = (((ks * 4 + rb) * 2 + h) * 32 + gg * 4 + tt) * 2 + w;
            sAh[idx] = hi; sAl[idx] = lo;
        }
        // ---- stage W (straight copy, already frag layout) ----
        {
            const uint2* srcH = (const uint2*)g_whi + kc * 4096;
            const uint2* srcL = (const uint2*)g_wlo + kc * 4096;
            uint2* dH = (uint2*)sWh; uint2* dL = (uint2*)sWl;
            for (int u = tid; u < 4096; u += 256) {
                dH[u] = __ldg(srcH + u);
                dL[u] = __ldg(srcL + u);
            }
        }
        __syncthreads();

#pragma unroll
        for (int ks = 0; ks < 4; ++ks) {
            uint2 ah[2][2], al[2][2];
#pragma unroll
            for (int mt = 0; mt < 2; ++mt) {
                int ab = (((ks * 4 + wm * 2 + mt) * 2) * 32 + lane) * 2;
                ah[mt][0] = *(const uint2*)(sAh + ab);
                ah[mt][1] = *(const uint2*)(sAh + ab + 64);
                al[mt][0] = *(const uint2*)(sAl + ab);
                al[mt][1] = *(const uint2*)(sAl + ab + 64);
            }
#pragma unroll
            for (int nt = 0; nt < 8; ++nt) {
                int bidx = ((ks * 32 + wn * 8 + nt) * 32 + lane) * 2;
                uint2 bh = *(const uint2*)(sWh + bidx);
                uint2 bl = *(const uint2*)(sWl + bidx);
#pragma unroll
                for (int mt = 0; mt < 2; ++mt) {
                    MMA(acc[mt][nt], ah[mt][0].x, ah[mt][1].x, ah[mt][0].y, ah[mt][1].y, bh.x, bh.y);
                    MMA(acc[mt][nt], ah[mt][0].x, ah[mt][1].x, ah[mt][0].y, ah[mt][1].y, bl.x, bl.y);
                    MMA(acc[mt][nt], al[mt][0].x, al[mt][1].x, al[mt][0].y, al[mt][1].y, bh.x, bh.y);
                }
            }
        }
        __syncthreads();
    }

    // ---- epilogue: + bias, LN1, GELU, write split-bf16 h (frag layout) ----
#pragma unroll
    for (int nt = 0; nt < 8; ++nt) {
        int col = wn * 64 + nt * 8 + t4 * 2;
        float b0 = __ldg(b_l + col), b1 = __ldg(b_l + col + 1);
#pragma unroll
        for (int mt = 0; mt < 2; ++mt) {
            acc[mt][nt][0] += b0; acc[mt][nt][1] += b1;
            acc[mt][nt][2] += b0; acc[mt][nt][3] += b1;
        }
    }
#pragma unroll
    for (int mt = 0; mt < 2; ++mt) {
        float s0 = 0.f, q0 = 0.f, s1 = 0.f, q1 = 0.f;
#pragma unroll
        for (int nt = 0; nt < 8; ++nt) {
            float c0 = acc[mt][nt][0], c1 = acc[mt][nt][1];
            float c2 = acc[mt][nt][2], c3 = acc[mt][nt][3];
            s0 += c0 + c1; q0 += c0 * c0 + c1 * c1;
            s1 += c2 + c3; q1 += c2 * c2 + c3 * c3;
        }
#pragma unroll
        for (int d = 1; d < 4; d <<= 1) {
            s0 += __shfl_xor_sync(0xffffffffu, s0, d);
            q0 += __shfl_xor_sync(0xffffffffu, q0, d);
            s1 += __shfl_xor_sync(0xffffffffu, s1, d);
            q1 += __shfl_xor_sync(0xffffffffu, q1, d);
        }
        if (t4 == 0) {
            int r = wm * 32 + mt * 16 + g;
            sSum[r][wn] = s0; sSq[r][wn] = q0;
            sSum[r + 8][wn] = s1; sSq[r + 8][wn] = q1;
        }
    }
    __syncthreads();

    size_t bb = (size_t)blockIdx.x * 8192;
#pragma unroll
    for (int mt = 0; mt < 2; ++mt) {
#pragma unroll
        for (int ro = 0; ro < 2; ++ro) {
            int r = wm * 32 + mt * 16 + g + ro * 8;
            int grow = row0 + r;
            float S  = sSum[r][0] + sSum[r][1] + sSum[r][2] + sSum[r][3];
            float SQ = sSq[r][0]  + sSq[r][1]  + sSq[r][2]  + sSq[r][3];
            float mu   = S * (1.0f / HID);
            float var  = SQ * (1.0f / HID) - mu * mu;
            float rstd = rsqrtf(var + 1e-5f);
            if (grow >= NUM_DST) continue;
            int rb = r >> 4, h = (r >> 3) & 1;
#pragma unroll
            for (int nt = 0; nt < 8; ++nt) {
                int col = wn * 64 + nt * 8 + t4 * 2;
                float c0 = acc[mt][nt][ro * 2], c1 = acc[mt][nt][ro * 2 + 1];
                float v0 = gelu_exact((c0 - mu) * rstd * __ldg(ln_g + col)     + __ldg(ln_b + col));
                float v1 = gelu_exact((c1 - mu) * rstd * __ldg(ln_g + col + 1) + __ldg(ln_b + col + 1));
                uint32_t hi, lo; split2(v0, v1, hi, lo);
                int idx = ((((wn * 4 + (nt >> 1)) * 4 + rb) * 2 + h) * 32 + lane) * 2 + (nt & 1);
                g_hh[bb + idx] = hi;
                g_hl[bb + idx] = lo;
            }
        }
    }
}

// ---------------------------------------------------------------------------
// K4: gemm2 — out = LN2( h @ W_out + b_out )  -> d_out fp32
// CTA 64 rows x 128 cols, 8 warps (2m x 4n), warp tile 32x32.
// smem (u32): Ah[2048] Al[2048] Wh[4096] Wl[4096] = 48 KB dynamic.
// ---------------------------------------------------------------------------
#define G2_SMEM (12288 * 4)
__global__ __launch_bounds__(256, 2)
void gemm2_tc(const float* __restrict__ b_out,
              const float* __restrict__ ln_g,
              const float* __restrict__ ln_b,
              float* __restrict__ out) {
    extern __shared__ uint32_t sm[];
    uint32_t* sAh = sm;
    uint32_t* sAl = sm + 2048;
    uint32_t* sWh = sm + 4096;
    uint32_t* sWl = sm + 8192;
    __shared__ float sSum[64][4], sSq[64][4];

    int tid = threadIdx.x, wid = tid >> 5, lane = tid & 31;
    int wm = wid >> 2, wn = wid & 3;
    int g = lane >> 2, t4 = lane & 3;
    int row0 = blockIdx.x * 64;
    size_t bb = (size_t)blockIdx.x * 8192;

    float acc[2][4][4];
#pragma unroll
    for (int mt = 0; mt < 2; ++mt)
#pragma unroll
        for (int nt = 0; nt < 4; ++nt)
#pragma unroll
            for (int j = 0; j < 4; ++j) acc[mt][nt][j] = 0.f;

    for (int kc = 0; kc < 4; ++kc) {
        {
            const uint2* sAH = (const uint2*)(g_hh + bb + kc * 2048);
            const uint2* sAL = (const uint2*)(g_hl + bb + kc * 2048);
            const uint2* sWH = (const uint2*)g_wohi + kc * 2048;
            const uint2* sWL = (const uint2*)g_wolo + kc * 2048;
            uint2* dAh = (uint2*)sAh; uint2* dAl = (uint2*)sAl;
            uint2* dWh = (uint2*)sWh; uint2* dWl = (uint2*)sWl;
            for (int u = tid; u < 1024; u += 256) {
                dAh[u] = __ldg(sAH + u);
                dAl[u] = __ldg(sAL + u);
            }
            for (int u = tid; u < 2048; u += 256) {
                dWh[u] = __ldg(sWH + u);
                dWl[u] = __ldg(sWL + u);
            }
        }
        __syncthreads();

#pragma unroll
        for (int ks = 0; ks < 4; ++ks) {
            uint2 ah[2][2], al[2][2];
#pragma unroll
            for (int mt = 0; mt < 2; ++mt) {
                int ab = (((ks * 4 + wm * 2 + mt) * 2) * 32 + lane) * 2;
                ah[mt][0] = *(const uint2*)(sAh + ab);
                ah[mt][1] = *(const uint2*)(sAh + ab + 64);
                al[mt][0] = *(const uint2*)(sAl + ab);
                al[mt][1] = *(const uint2*)(sAl + ab + 64);
            }
#pragma unroll
            for (int nt = 0; nt < 4; ++nt) {
                int bidx = ((ks * 16 + wn * 4 + nt) * 32 + lane) * 2;
                uint2 bh = *(const uint2*)(sWh + bidx);
                uint2 bl = *(const uint2*)(sWl + bidx);
#pragma unroll
                for (int mt = 0; mt < 2; ++mt) {
                    MMA(acc[mt][nt], ah[mt][0].x, ah[mt][1].x, ah[mt][0].y, ah[mt][1].y, bh.x, bh.y);
                    MMA(acc[mt][nt], ah[mt][0].x, ah[mt][1].x, ah[mt][0].y, ah[mt][1].y, bl.x, bl.y);
                    MMA(acc[mt][nt], al[mt][0].x, al[mt][1].x, al[mt][0].y, al[mt][1].y, bh.x, bh.y);
                }
            }
        }
        __syncthreads();
    }

    // ---- epilogue: + bias, LN2, fp32 out ----
#pragma unroll
    for (int nt = 0; nt < 4; ++nt) {
        int col = wn * 32 + nt * 8 + t4 * 2;
        float b0 = __ldg(b_out + col), b1 = __ldg(b_out + col + 1);
#pragma unroll
        for (int mt = 0; mt < 2; ++mt) {
            acc[mt][nt][0] += b0; acc[mt][nt][1] += b1;
            acc[mt][nt][2] += b0; acc[mt][nt][3] += b1;
        }
    }
#pragma unroll
    for (int mt = 0; mt < 2; ++mt) {
        float s0 = 0.f, q0 = 0.f, s1 = 0.f, q1 = 0.f;
#pragma unroll
        for (int nt = 0; nt < 4; ++nt) {
            float c0 = acc[mt][nt][0], c1 = acc[mt][nt][1];
            float c2 = acc[mt][nt][2], c3 = acc[mt][nt][3];
            s0 += c0 + c1; q0 += c0 * c0 + c1 * c1;
            s1 += c2 + c3; q1 += c2 * c2 + c3 * c3;
        }
#pragma unroll
        for (int d = 1; d < 4; d <<= 1) {
            s0 += __shfl_xor_sync(0xffffffffu, s0, d);
            q0 += __shfl_xor_sync(0xffffffffu, q0, d);
            s1 += __shfl_xor_sync(0xffffffffu, s1, d);
            q1 += __shfl_xor_sync(0xffffffffu, q1, d);
        }
        if (t4 == 0) {
            int r = wm * 32 + mt * 16 + g;
            sSum[r][wn] = s0; sSq[r][wn] = q0;
            sSum[r + 8][wn] = s1; sSq[r + 8][wn] = q1;
        }
    }
    __syncthreads();

#pragma unroll
    for (int mt = 0; mt < 2; ++mt) {
#pragma unroll
        for (int ro = 0; ro < 2; ++ro) {
            int r = wm * 32 + mt * 16 + g + ro * 8;
            int grow = row0 + r;
            float S  = sSum[r][0] + sSum[r][1] + sSum[r][2] + sSum[r][3];
            float SQ = sSq[r][0]  + sSq[r][1]  + sSq[r][2]  + sSq[r][3];
            float mu   = S * (1.0f / OUT_DIM);
            float var  = SQ * (1.0f / OUT_DIM) - mu * mu;
            float rstd = rsqrtf(var + 1e-5f);
            if (grow >= NUM_DST) continue;
#pragma unroll
            for (int nt = 0; nt < 4; ++nt) {
                int col = wn * 32 + nt * 8 + t4 * 2;
                float c0 = acc[mt][nt][ro * 2], c1 = acc[mt][nt][ro * 2 + 1];
                float2 o;
                o.x = (c0 - mu) * rstd * __ldg(ln_g + col)     + __ldg(ln_b + col);
                o.y = (c1 - mu) * rstd * __ldg(ln_g + col + 1) + __ldg(ln_b + col + 1);
                *(float2*)(out + (size_t)grow * 128 + col) = o;
            }
        }
    }
}

// ---------------------------------------------------------------------------
extern "C" void kernel_launch(void* const* d_in, const int* in_sizes, int n_in,
                              void* d_out, int out_size) {
    const float* x     = (const float*)d_in[0];
    const float* w_l   = (const float*)d_in[1];
    const float* b_l   = (const float*)d_in[2];
    const float* w_r   = (const float*)d_in[3];
    const float* ln1_g = (const float*)d_in[4];
    const float* ln1_b = (const float*)d_in[5];
    const float* w_out = (const float*)d_in[6];
    const float* b_out = (const float*)d_in[7];
    const float* ln2_g = (const float*)d_in[8];
    const float* ln2_b = (const float*)d_in[9];
    const int*   esrc  = (const int*)d_in[10];
    const int*   edst  = (const int*)d_in[11];
    float* out = (float*)d_out;

    cudaFuncSetAttribute(gemm1_tc, cudaFuncAttributeMaxDynamicSharedMemorySize, G1_SMEM);
    cudaFuncSetAttribute(gemm2_tc, cudaFuncAttributeMaxDynamicSharedMemorySize, G2_SMEM);

    zero_kernel<<<1024, 256>>>();
    edge_kernel<<<NUM_EDGES / 8, 256>>>(x, esrc, edst);
    prep_kernel<<<192, 256>>>(w_l, w_r, w_out);

    gemm1_tc<<<NRB, 256, G1_SMEM>>>(x, b_l, ln1_g, ln1_b);
    gemm2_tc<<<NRB, 256, G2_SMEM>>>(b_out, ln2_g, ln2_b, out);
}

// round 8
// speedup vs baseline: 1.5921x; 1.0686x over previous
#include <cuda_runtime.h>
#include <cuda_bf16.h>
#include <math.h>
#include <stdint.h>

#define NUM_SRC   200000
#define NUM_DST   100000
#define NUM_EDGES 1600000
#define IN_DIM    128
#define HID       256
#define OUT_DIM   128
#define NRB       1563      // ceil(NUM_DST/64)

// ---------------------------------------------------------------------------
// Scratch (__device__ globals; no allocation allowed)
// ---------------------------------------------------------------------------
__device__ __align__(16) float    g_accum[(size_t)NUM_DST * IN_DIM];   // 51.2 MB
__device__ __align__(16) float    g_cnt[NUM_DST];
__device__ __align__(16) uint32_t g_ah[(size_t)NUM_DST * 128];         // A=[mean|x] bf16 hi, [row][kp]
__device__ __align__(16) uint32_t g_al[(size_t)NUM_DST * 128];         // A lo
__device__ __align__(16) uint32_t g_hh[(size_t)NUM_DST * 128];         // h bf16 hi, [row][kp]
__device__ __align__(16) uint32_t g_hl[(size_t)NUM_DST * 128];         // h lo
__device__ __align__(16) uint32_t g_wh[256 * 128];                     // W_cat hi  [n][kp]
__device__ __align__(16) uint32_t g_wl[256 * 128];                     // W_cat lo
__device__ __align__(16) uint32_t g_wohi[128 * 128];                   // W_out hi  [n][kp]
__device__ __align__(16) uint32_t g_wolo[128 * 128];                   // W_out lo

// ---------------------------------------------------------------------------
// helpers
// ---------------------------------------------------------------------------
__device__ __forceinline__ uint32_t smem_u32(const void* p) {
    uint32_t a;
    asm("{ .reg .u64 t; cvta.to.shared.u64 t, %1; cvt.u32.u64 %0, t; }" : "=r"(a) : "l"(p));
    return a;
}
__device__ __forceinline__ void split2(float a0, float a1, uint32_t& hi, uint32_t& lo) {
    __nv_bfloat16 h0 = __float2bfloat16(a0), h1 = __float2bfloat16(a1);
    __nv_bfloat16 l0 = __float2bfloat16(a0 - __bfloat162float(h0));
    __nv_bfloat16 l1 = __float2bfloat16(a1 - __bfloat162float(h1));
    __nv_bfloat162 H; H.x = h0; H.y = h1;
    __nv_bfloat162 L; L.x = l0; L.y = l1;
    hi = *(uint32_t*)&H; lo = *(uint32_t*)&L;
}
__device__ __forceinline__ float gelu_exact(float t) {
    return 0.5f * t * (1.0f + erff(t * 0.70710678118654752f));
}

#define MMA(c, A0, A1, A2, A3, B0, B1)                                          \
    asm("mma.sync.aligned.m16n8k16.row.col.f32.bf16.bf16.f32 "                  \
        "{%0,%1,%2,%3},{%4,%5,%6,%7},{%8,%9},{%0,%1,%2,%3};"                    \
        : "+f"((c)[0]), "+f"((c)[1]), "+f"((c)[2]), "+f"((c)[3])                \
        : "r"(A0), "r"(A1), "r"(A2), "r"(A3), "r"(B0), "r"(B1))

#define LDSM4(R, addr)                                                          \
    asm volatile("ldmatrix.sync.aligned.m8n8.x4.shared.b16 {%0,%1,%2,%3}, [%4];"\
        : "=r"((R)[0]), "=r"((R)[1]), "=r"((R)[2]), "=r"((R)[3]) : "r"(addr))

#define CPA(dst, src, sz)                                                       \
    asm volatile("cp.async.ca.shared.global [%0], [%1], 16, %2;"                \
        :: "r"(dst), "l"(src), "r"(sz))
#define CPA16(dst, src)                                                         \
    asm volatile("cp.async.ca.shared.global [%0], [%1], 16;" :: "r"(dst), "l"(src))
#define CPCOMMIT() asm volatile("cp.async.commit_group;" ::: "memory")

// ---------------------------------------------------------------------------
// K0: zero accum + cnt
// ---------------------------------------------------------------------------
__global__ void zero_kernel() {
    const int n4_accum = (NUM_DST * IN_DIM) / 4;
    const int n4_cnt   = NUM_DST / 4;
    float4 z = make_float4(0.f, 0.f, 0.f, 0.f);
    int stride = gridDim.x * blockDim.x;
    for (int i = blockIdx.x * blockDim.x + threadIdx.x; i < n4_accum; i += stride)
        ((float4*)g_accum)[i] = z;
    for (int i = blockIdx.x * blockDim.x + threadIdx.x; i < n4_cnt; i += stride)
        ((float4*)g_cnt)[i] = z;
}

// ---------------------------------------------------------------------------
// K1: edge scatter-add. One warp per edge, one float4 per lane.
// ---------------------------------------------------------------------------
__global__ void edge_kernel(const float* __restrict__ x,
                            const int* __restrict__ esrc,
                            const int* __restrict__ edst) {
    int e    = blockIdx.x * 8 + (threadIdx.x >> 5);
    int lane = threadIdx.x & 31;
    if (e >= NUM_EDGES) return;
    int s = __ldg(esrc + e);
    int d = __ldg(edst + e);
    float4 v = __ldg(((const float4*)(x + (size_t)s * IN_DIM)) + lane);
    float* outp = g_accum + (size_t)d * IN_DIM + lane * 4;
    asm volatile("red.global.add.v4.f32 [%0], {%1,%2,%3,%4};"
                 :: "l"(outp), "f"(v.x), "f"(v.y), "f"(v.z), "f"(v.w) : "memory");
    if (lane == 0) {
        float one = 1.0f;
        asm volatile("red.global.add.f32 [%0], %1;" :: "l"(g_cnt + d), "f"(one) : "memory");
    }
}

// ---------------------------------------------------------------------------
// K2: prep_w — split weights to bf16 hi/lo, [n][kp] layout.
// ---------------------------------------------------------------------------
__global__ void prep_w(const float* __restrict__ w_l,
                       const float* __restrict__ w_r,
                       const float* __restrict__ w_out) {
    int t = blockIdx.x * 256 + threadIdx.x;       // 0..49151
    if (t < 32768) {
        int kp = t >> 8, n = t & 255;
        int k0 = 2 * kp;
        float v0, v1;
        if (k0 < 128) { v0 = w_l[k0 * 256 + n];         v1 = w_l[(k0 + 1) * 256 + n]; }
        else          { v0 = w_r[(k0 - 128) * 256 + n]; v1 = w_r[(k0 - 127) * 256 + n]; }
        uint32_t hi, lo; split2(v0, v1, hi, lo);
        g_wh[n * 128 + kp] = hi; g_wl[n * 128 + kp] = lo;
    } else {
        int u = t - 32768;
        int kp = u >> 7, n = u & 127;
        int k0 = 2 * kp;
        float v0 = w_out[k0 * 128 + n], v1 = w_out[(k0 + 1) * 128 + n];
        uint32_t hi, lo; split2(v0, v1, hi, lo);
        g_wohi[n * 128 + kp] = hi; g_wolo[n * 128 + kp] = lo;
    }
}

// ---------------------------------------------------------------------------
// K3: prep_a — A = [mean_nbr | x_tgt] split to bf16 hi/lo, [row][kp]. Coalesced.
// ---------------------------------------------------------------------------
__global__ void prep_a(const float* __restrict__ x) {
    int t = blockIdx.x * 256 + threadIdx.x;     // NUM_DST*64 threads, 1 float4 each
    if (t >= NUM_DST * 64) return;
    int row = t >> 6, kq = t & 63;              // kq-th float4 of the 256-wide row
    float4 v;
    if (kq < 32) {
        float inv = 1.0f / fmaxf(g_cnt[row], 1.0f);
        v = ((const float4*)g_accum)[(size_t)row * 32 + kq];
        v.x *= inv; v.y *= inv; v.z *= inv; v.w *= inv;
    } else {
        v = __ldg(((const float4*)x) + (size_t)row * 32 + (kq - 32));
    }
    uint32_t h0, l0, h1, l1;
    split2(v.x, v.y, h0, l0);
    split2(v.z, v.w, h1, l1);
    ((uint2*)g_ah)[(size_t)row * 64 + kq] = make_uint2(h0, h1);
    ((uint2*)g_al)[(size_t)row * 64 + kq] = make_uint2(l0, l1);
}

// ---------------------------------------------------------------------------
// K4: gemm1 — h = gelu(LN1( A @ W_cat + b_l )) -> g_hh/g_hl
// CTA 64 rows x 256 cols, 512 thr (16 warps: 2m x 8n, warp tile 32x32).
// K=256 in 4 chunks of 64, cp.async double buffered + ldmatrix (swizzled).
// Stage (bytes): Ah 8K @0, Al 8K @8192, Wh 32K @16384, Wl 32K @49152. x2 = 160KB.
// ---------------------------------------------------------------------------
#define G1_SMEM 163840
__global__ __launch_bounds__(512, 1)
void gemm1_tc(const float* __restrict__ b_l,
              const float* __restrict__ ln_g,
              const float* __restrict__ ln_b) {
    extern __shared__ uint32_t sm[];
    __shared__ float sSum[64][8], sSq[64][8];
    uint32_t sb = smem_u32(sm);

    int tid = threadIdx.x, wid = tid >> 5, lane = tid & 31;
    int wm = wid >> 3, wn = wid & 7;
    int g = lane >> 2, t4 = lane & 3;
    int row0 = blockIdx.x * 64;

    // cp.async thread mapping
    int ar = tid >> 3, ac = tid & 7;                 // A: one 16B chunk each
    int agrow = row0 + ar;
    uint32_t asz = (agrow < NUM_DST) ? 16u : 0u;
    uint32_t adst = (uint32_t)(ar * 8 + (ac ^ (ar & 7))) * 16;
    const uint32_t* asrcH = g_ah + (size_t)agrow * 128 + ac * 4;
    const uint32_t* asrcL = g_al + (size_t)agrow * 128 + ac * 4;

    float acc[2][4][4];
#pragma unroll
    for (int mt = 0; mt < 2; ++mt)
#pragma unroll
        for (int nt = 0; nt < 4; ++nt)
#pragma unroll
            for (int j = 0; j < 4; ++j) acc[mt][nt][j] = 0.f;

#define G1_ISSUE(kc, s) do {                                                      \
        uint32_t base = sb + (s) * 81920;                                         \
        CPA(base + adst, asrcH + (kc) * 32, asz);                                 \
        CPA(base + 8192 + adst, asrcL + (kc) * 32, asz);                          \
        for (int i = tid; i < 2048; i += 512) {                                   \
            int n_ = i >> 3, c_ = i & 7;                                          \
            uint32_t d_ = base + 16384 + (uint32_t)(n_ * 8 + (c_ ^ (n_ & 7))) * 16;\
            CPA16(d_, g_wh + n_ * 128 + (kc) * 32 + c_ * 4);                      \
            CPA16(d_ + 32768, g_wl + n_ * 128 + (kc) * 32 + c_ * 4);              \
        }                                                                         \
        CPCOMMIT();                                                               \
    } while (0)

    G1_ISSUE(0, 0);

    // ldmatrix per-lane address precompute
    int arow = (lane & 15);
    int asel = lane >> 4;
    int wrow = ((lane >> 4) << 3) + (lane & 7);
    int wsel = (lane >> 3) & 1;

    for (int kc = 0; kc < 4; ++kc) {
        if (kc < 3) {
            G1_ISSUE(kc + 1, (kc + 1) & 1);
            asm volatile("cp.async.wait_group 1;" ::: "memory");
        } else {
            asm volatile("cp.async.wait_group 0;" ::: "memory");
        }
        __syncthreads();
        uint32_t base = sb + (kc & 1) * 81920;

#pragma unroll
        for (int ks = 0; ks < 4; ++ks) {
            uint32_t a_h[2][4], a_l[2][4], b_h[2][4], b_l2[2][4];
#pragma unroll
            for (int mt = 0; mt < 2; ++mt) {
                int r = wm * 32 + mt * 16 + arow;
                uint32_t ad = base + (uint32_t)(r * 8 + ((2 * ks + asel) ^ (r & 7))) * 16;
                LDSM4(a_h[mt], ad);
                LDSM4(a_l[mt], ad + 8192);
            }
#pragma unroll
            for (int ntp = 0; ntp < 2; ++ntp) {
                int n_ = wn * 32 + ntp * 16 + wrow;
                uint32_t wd = base + 16384 + (uint32_t)(n_ * 8 + ((2 * ks + wsel) ^ (n_ & 7))) * 16;
                LDSM4(b_h[ntp], wd);
                LDSM4(b_l2[ntp], wd + 32768);
            }
#pragma unroll
            for (int nt = 0; nt < 4; ++nt) {
                uint32_t bh0 = b_h[nt >> 1][(nt & 1) * 2], bh1 = b_h[nt >> 1][(nt & 1) * 2 + 1];
                uint32_t bl0 = b_l2[nt >> 1][(nt & 1) * 2], bl1 = b_l2[nt >> 1][(nt & 1) * 2 + 1];
#pragma unroll
                for (int mt = 0; mt < 2; ++mt) {
                    MMA(acc[mt][nt], a_h[mt][0], a_h[mt][1], a_h[mt][2], a_h[mt][3], bh0, bh1);
                    MMA(acc[mt][nt], a_h[mt][0], a_h[mt][1], a_h[mt][2], a_h[mt][3], bl0, bl1);
                    MMA(acc[mt][nt], a_l[mt][0], a_l[mt][1], a_l[mt][2], a_l[mt][3], bh0, bh1);
                }
            }
        }
        __syncthreads();
    }

    // ---- epilogue: bias, LN1, GELU, write split-bf16 h [row][kp] ----
#pragma unroll
    for (int nt = 0; nt < 4; ++nt) {
        int col = wn * 32 + nt * 8 + t4 * 2;
        float b0 = __ldg(b_l + col), b1 = __ldg(b_l + col + 1);
#pragma unroll
        for (int mt = 0; mt < 2; ++mt) {
            acc[mt][nt][0] += b0; acc[mt][nt][1] += b1;
            acc[mt][nt][2] += b0; acc[mt][nt][3] += b1;
        }
    }
#pragma unroll
    for (int mt = 0; mt < 2; ++mt)
#pragma unroll
        for (int ro = 0; ro < 2; ++ro) {
            float s = 0.f, q = 0.f;
#pragma unroll
            for (int nt = 0; nt < 4; ++nt) {
                float c0 = acc[mt][nt][ro * 2], c1 = acc[mt][nt][ro * 2 + 1];
                s += c0 + c1; q += c0 * c0 + c1 * c1;
            }
            s += __shfl_xor_sync(0xffffffffu, s, 1); q += __shfl_xor_sync(0xffffffffu, q, 1);
            s += __shfl_xor_sync(0xffffffffu, s, 2); q += __shfl_xor_sync(0xffffffffu, q, 2);
            if (t4 == 0) {
                int r = wm * 32 + mt * 16 + ro * 8 + g;
                sSum[r][wn] = s; sSq[r][wn] = q;
            }
        }
    __syncthreads();

#pragma unroll
    for (int mt = 0; mt < 2; ++mt)
#pragma unroll
        for (int ro = 0; ro < 2; ++ro) {
            int r = wm * 32 + mt * 16 + ro * 8 + g;
            int grow = row0 + r;
            float S = 0.f, SQ = 0.f;
#pragma unroll
            for (int j = 0; j < 8; ++j) { S += sSum[r][j]; SQ += sSq[r][j]; }
            float mu   = S * (1.0f / HID);
            float var  = SQ * (1.0f / HID) - mu * mu;
            float rstd = rsqrtf(var + 1e-5f);
            if (grow >= NUM_DST) continue;
#pragma unroll
            for (int nt = 0; nt < 4; ++nt) {
                int col = wn * 32 + nt * 8 + t4 * 2;
                float c0 = acc[mt][nt][ro * 2], c1 = acc[mt][nt][ro * 2 + 1];
                float v0 = gelu_exact((c0 - mu) * rstd * __ldg(ln_g + col)     + __ldg(ln_b + col));
                float v1 = gelu_exact((c1 - mu) * rstd * __ldg(ln_g + col + 1) + __ldg(ln_b + col + 1));
                uint32_t hi, lo; split2(v0, v1, hi, lo);
                g_hh[(size_t)grow * 128 + (col >> 1)] = hi;
                g_hl[(size_t)grow * 128 + (col >> 1)] = lo;
            }
        }
}

// ---------------------------------------------------------------------------
// K5: gemm2 — out = LN2( h @ W_out + b_out ) -> d_out fp32
// CTA 64 rows x 128 cols, 512 thr (16 warps: 2m x 8n, warp tile 32x16).
// Stage (bytes): Ah 8K @0, Al 8K @8192, Wh 16K @16384, Wl 16K @32768. x2 = 96KB.
// ---------------------------------------------------------------------------
#define G2_SMEM 98304
__global__ __launch_bounds__(512, 2)
void gemm2_tc(const float* __restrict__ b_out,
              const float* __restrict__ ln_g,
              const float* __restrict__ ln_b,
              float* __restrict__ out) {
    extern __shared__ uint32_t sm[];
    __shared__ float sSum[64][8], sSq[64][8];
    uint32_t sb = smem_u32(sm);

    int tid = threadIdx.x, wid = tid >> 5, lane = tid & 31;
    int wm = wid >> 3, wn = wid & 7;
    int g = lane >> 2, t4 = lane & 3;
    int row0 = blockIdx.x * 64;

    int ar = tid >> 3, ac = tid & 7;
    int agrow = row0 + ar;
    uint32_t asz = (agrow < NUM_DST) ? 16u : 0u;
    uint32_t adst = (uint32_t)(ar * 8 + (ac ^ (ar & 7))) * 16;
    const uint32_t* asrcH = g_hh + (size_t)agrow * 128 + ac * 4;
    const uint32_t* asrcL = g_hl + (size_t)agrow * 128 + ac * 4;

    float acc[2][2][4];
#pragma unroll
    for (int mt = 0; mt < 2; ++mt)
#pragma unroll
        for (int nt = 0; nt < 2; ++nt)
#pragma unroll
            for (int j = 0; j < 4; ++j) acc[mt][nt][j] = 0.f;

#define G2_ISSUE(kc, s) do {                                                      \
        uint32_t base = sb + (s) * 49152;                                         \
        CPA(base + adst, asrcH + (kc) * 32, asz);                                 \
        CPA(base + 8192 + adst, asrcL + (kc) * 32, asz);                          \
        for (int i = tid; i < 1024; i += 512) {                                   \
            int n_ = i >> 3, c_ = i & 7;                                          \
            uint32_t d_ = base + 16384 + (uint32_t)(n_ * 8 + (c_ ^ (n_ & 7))) * 16;\
            CPA16(d_, g_wohi + n_ * 128 + (kc) * 32 + c_ * 4);                    \
            CPA16(d_ + 16384, g_wolo + n_ * 128 + (kc) * 32 + c_ * 4);            \
        }                                                                         \
        CPCOMMIT();                                                               \
    } while (0)

    G2_ISSUE(0, 0);

    int arow = (lane & 15);
    int asel = lane >> 4;
    int wrow = ((lane >> 4) << 3) + (lane & 7);
    int wsel = (lane >> 3) & 1;

    for (int kc = 0; kc < 4; ++kc) {
        if (kc < 3) {
            G2_ISSUE(kc + 1, (kc + 1) & 1);
            asm volatile("cp.async.wait_group 1;" ::: "memory");
        } else {
            asm volatile("cp.async.wait_group 0;" ::: "memory");
        }
        __syncthreads();
        uint32_t base = sb + (kc & 1) * 49152;

#pragma unroll
        for (int ks = 0; ks < 4; ++ks) {
            uint32_t a_h[2][4], a_l[2][4], b_h[4], b_l2[4];
#pragma unroll
            for (int mt = 0; mt < 2; ++mt) {
                int r = wm * 32 + mt * 16 + arow;
                uint32_t ad = base + (uint32_t)(r * 8 + ((2 * ks + asel) ^ (r & 7))) * 16;
                LDSM4(a_h[mt], ad);
                LDSM4(a_l[mt], ad + 8192);
            }
            {
                int n_ = wn * 16 + wrow;
                uint32_t wd = base + 16384 + (uint32_t)(n_ * 8 + ((2 * ks + wsel) ^ (n_ & 7))) * 16;
                LDSM4(b_h, wd);
                LDSM4(b_l2, wd + 16384);
            }
#pragma unroll
            for (int nt = 0; nt < 2; ++nt) {
                uint32_t bh0 = b_h[nt * 2], bh1 = b_h[nt * 2 + 1];
                uint32_t bl0 = b_l2[nt * 2], bl1 = b_l2[nt * 2 + 1];
#pragma unroll
                for (int mt = 0; mt < 2; ++mt) {
                    MMA(acc[mt][nt], a_h[mt][0], a_h[mt][1], a_h[mt][2], a_h[mt][3], bh0, bh1);
                    MMA(acc[mt][nt], a_h[mt][0], a_h[mt][1], a_h[mt][2], a_h[mt][3], bl0, bl1);
                    MMA(acc[mt][nt], a_l[mt][0], a_l[mt][1], a_l[mt][2], a_l[mt][3], bh0, bh1);
                }
            }
        }
        __syncthreads();
    }

    // ---- epilogue: bias, LN2, fp32 out ----
#pragma unroll
    for (int nt = 0; nt < 2; ++nt) {
        int col = wn * 16 + nt * 8 + t4 * 2;
        float b0 = __ldg(b_out + col), b1 = __ldg(b_out + col + 1);
#pragma unroll
        for (int mt = 0; mt < 2; ++mt) {
            acc[mt][nt][0] += b0; acc[mt][nt][1] += b1;
            acc[mt][nt][2] += b0; acc[mt][nt][3] += b1;
        }
    }
#pragma unroll
    for (int mt = 0; mt < 2; ++mt)
#pragma unroll
        for (int ro = 0; ro < 2; ++ro) {
            float s = 0.f, q = 0.f;
#pragma unroll
            for (int nt = 0; nt < 2; ++nt) {
                float c0 = acc[mt][nt][ro * 2], c1 = acc[mt][nt][ro * 2 + 1];
                s += c0 + c1; q += c0 * c0 + c1 * c1;
            }
            s += __shfl_xor_sync(0xffffffffu, s, 1); q += __shfl_xor_sync(0xffffffffu, q, 1);
            s += __shfl_xor_sync(0xffffffffu, s, 2); q += __shfl_xor_sync(0xffffffffu, q, 2);
            if (t4 == 0) {
                int r = wm * 32 + mt * 16 + ro * 8 + g;
                sSum[r][wn] = s; sSq[r][wn] = q;
            }
        }
    __syncthreads();

#pragma unroll
    for (int mt = 0; mt < 2; ++mt)
#pragma unroll
        for (int ro = 0; ro < 2; ++ro) {
            int r = wm * 32 + mt * 16 + ro * 8 + g;
            int grow = row0 + r;
            float S = 0.f, SQ = 0.f;
#pragma unroll
            for (int j = 0; j < 8; ++j) { S += sSum[r][j]; SQ += sSq[r][j]; }
            float mu   = S * (1.0f / OUT_DIM);
            float var  = SQ * (1.0f / OUT_DIM) - mu * mu;
            float rstd = rsqrtf(var + 1e-5f);
            if (grow >= NUM_DST) continue;
#pragma unroll
            for (int nt = 0; nt < 2; ++nt) {
                int col = wn * 16 + nt * 8 + t4 * 2;
                float c0 = acc[mt][nt][ro * 2], c1 = acc[mt][nt][ro * 2 + 1];
                float2 o;
                o.x = (c0 - mu) * rstd * __ldg(ln_g + col)     + __ldg(ln_b + col);
                o.y = (c1 - mu) * rstd * __ldg(ln_g + col + 1) + __ldg(ln_b + col + 1);
                *(float2*)(out + (size_t)grow * 128 + col) = o;
            }
        }
}

// ---------------------------------------------------------------------------
extern "C" void kernel_launch(void* const* d_in, const int* in_sizes, int n_in,
                              void* d_out, int out_size) {
    const float* x     = (const float*)d_in[0];
    const float* w_l   = (const float*)d_in[1];
    const float* b_l   = (const float*)d_in[2];
    const float* w_r   = (const float*)d_in[3];
    const float* ln1_g = (const float*)d_in[4];
    const float* ln1_b = (const float*)d_in[5];
    const float* w_out = (const float*)d_in[6];
    const float* b_out = (const float*)d_in[7];
    const float* ln2_g = (const float*)d_in[8];
    const float* ln2_b = (const float*)d_in[9];
    const int*   esrc  = (const int*)d_in[10];
    const int*   edst  = (const int*)d_in[11];
    float* out = (float*)d_out;

    cudaFuncSetAttribute(gemm1_tc, cudaFuncAttributeMaxDynamicSharedMemorySize, G1_SMEM);
    cudaFuncSetAttribute(gemm2_tc, cudaFuncAttributeMaxDynamicSharedMemorySize, G2_SMEM);

    zero_kernel<<<1024, 256>>>();
    edge_kernel<<<NUM_EDGES / 8, 256>>>(x, esrc, edst);
    prep_w<<<192, 256>>>(w_l, w_r, w_out);
    prep_a<<<(NUM_DST * 64 + 255) / 256, 256>>>(x);

    gemm1_tc<<<NRB, 512, G1_SMEM>>>(b_l, ln1_g, ln1_b);
    gemm2_tc<<<NRB, 512, G2_SMEM>>>(b_out, ln2_g, ln2_b, out);
}